// round 6
// baseline (speedup 1.0000x reference)
#include <cuda_runtime.h>
#include <cuda_bf16.h>
#include <cstdint>

#define FRONT 3072
#define EMBED 768
#define TOKENS 16384

// ---------------- device scratch (no dynamic alloc allowed) ----------------
__device__ __nv_bfloat16 g_W1hi[EMBED * FRONT];
__device__ __nv_bfloat16 g_W1lo[EMBED * FRONT];
__device__ __nv_bfloat16 g_W2hi[EMBED * EMBED];
__device__ __nv_bfloat16 g_W2lo[EMBED * EMBED];
__device__ __nv_bfloat16 g_Ahi[(size_t)TOKENS * FRONT];   // gathered, split embed
__device__ __nv_bfloat16 g_Alo[(size_t)TOKENS * FRONT];
__device__ __nv_bfloat16 g_Yhi[(size_t)TOKENS * EMBED];   // GELU(h1), split
__device__ __nv_bfloat16 g_Ylo[(size_t)TOKENS * EMBED];

// ---------------- tiling ----------------
constexpr int BM = 128;
constexpr int BN = 128;
constexpr int BK = 32;              // bf16 K columns per stage
constexpr int THREADS = 256;
constexpr int STAGES = 4;

constexpr int ROWB  = 80;           // padded bytes per smem row (64B data + 16B pad)
constexpr int MAT   = 128 * ROWB;   // 10240 B
constexpr int STAGE = 4 * MAT;      // Ahi, Alo, Bhi, Blo = 40960 B
constexpr int SMEM_TOTAL = STAGES * STAGE;  // 163840 B
constexpr int OFF_A_HI = 0;
constexpr int OFF_A_LO = MAT;
constexpr int OFF_B_HI = 2 * MAT;
constexpr int OFF_B_LO = 3 * MAT;

// ---------------- PTX helpers (plain compute_103-legal) ----------------
__device__ __forceinline__ uint32_t smem_u32(const void* p) {
    uint32_t a;
    asm("{ .reg .u64 t; cvta.to.shared.u64 t, %1; cvt.u32.u64 %0, t; }" : "=r"(a) : "l"(p));
    return a;
}
__device__ __forceinline__ void cp16(uint32_t s, const void* g) {
    asm volatile("cp.async.cg.shared.global [%0], [%1], 16;" :: "r"(s), "l"(g));
}
__device__ __forceinline__ void cp_commit() {
    asm volatile("cp.async.commit_group;");
}
__device__ __forceinline__ void ldm4(uint32_t r[4], uint32_t a) {
    asm volatile("ldmatrix.sync.aligned.m8n8.x4.shared.b16 {%0,%1,%2,%3}, [%4];"
                 : "=r"(r[0]), "=r"(r[1]), "=r"(r[2]), "=r"(r[3]) : "r"(a));
}
__device__ __forceinline__ void mma16816(float c[4], const uint32_t a[4],
                                         uint32_t b0, uint32_t b1) {
    asm volatile(
        "mma.sync.aligned.m16n8k16.row.col.f32.bf16.bf16.f32 "
        "{%0,%1,%2,%3}, {%4,%5,%6,%7}, {%8,%9}, {%0,%1,%2,%3};"
        : "+f"(c[0]), "+f"(c[1]), "+f"(c[2]), "+f"(c[3])
        : "r"(a[0]), "r"(a[1]), "r"(a[2]), "r"(a[3]), "r"(b0), "r"(b1));
}

__device__ __forceinline__ void split2(float x, float y, uint32_t& hi, uint32_t& lo) {
    __nv_bfloat162 h = __floats2bfloat162_rn(x, y);
    __nv_bfloat162 l = __floats2bfloat162_rn(x - __low2float(h), y - __high2float(h));
    hi = *(uint32_t*)&h;
    lo = *(uint32_t*)&l;
}

// ---------------- prep: weight split fp32 -> bf16 hi/lo ----------------
__global__ void convert_weights(const float* __restrict__ W1, const float* __restrict__ W2) {
    int i = blockIdx.x * blockDim.x + threadIdx.x;
    if (i < EMBED * FRONT) {
        float x = W1[i];
        __nv_bfloat16 h = __float2bfloat16(x);
        g_W1hi[i] = h;
        g_W1lo[i] = __float2bfloat16(x - __bfloat162float(h));
    }
    if (i < EMBED * EMBED) {
        float x = W2[i];
        __nv_bfloat16 h = __float2bfloat16(x);
        g_W2hi[i] = h;
        g_W2lo[i] = __float2bfloat16(x - __bfloat162float(h));
    }
}

// ---------------- prep: gather + split embedding rows ----------------
__global__ void __launch_bounds__(256, 4)
gather_split(const float* __restrict__ tok, const int* __restrict__ idxs) {
    const int row = blockIdx.x;
    const float4* src = (const float4*)(tok + (size_t)idxs[row] * FRONT);
    uint2* hi = (uint2*)(g_Ahi + (size_t)row * FRONT);
    uint2* lo = (uint2*)(g_Alo + (size_t)row * FRONT);
#pragma unroll
    for (int t = 0; t < FRONT / 4 / 256; ++t) {
        int i = t * 256 + threadIdx.x;
        float4 v = src[i];
        uint2 hv, lv;
        split2(v.x, v.y, hv.x, lv.x);
        split2(v.z, v.w, hv.y, lv.y);
        hi[i] = hv;
        lo[i] = lv;
    }
}

// ---------------- pure split-bf16 mma.sync GEMM, 4-stage cp.async ----------------
// acc = sum_k A[m,k]*B[n,k]   (AhBh + AhBl + AlBh)
// MODE 0: out fp32 = acc + bias
// MODE 1: v = gelu(acc + bias); write split bf16 to outHi/outLo
template <int MODE>
__global__ void __launch_bounds__(THREADS, 1)
gemm_mma(const __nv_bfloat16* __restrict__ Ahi,
         const __nv_bfloat16* __restrict__ Alo,
         const __nv_bfloat16* __restrict__ Bhi,
         const __nv_bfloat16* __restrict__ Blo,
         const float* __restrict__ bias,
         float* __restrict__ out,
         __nv_bfloat16* __restrict__ outHi,
         __nv_bfloat16* __restrict__ outLo,
         int K) {
    extern __shared__ char sm[];
    const uint32_t sb = smem_u32(sm);

    const int tid = threadIdx.x;
    const int wid = tid >> 5;
    const int l   = tid & 31;
    const int m0  = blockIdx.y * BM;
    const int n0  = blockIdx.x * BN;
    const int wm0 = (wid >> 2) * 64;
    const int wn0 = (wid & 3) * 32;

    // ---- stage loader: tid -> (row = tid&127, half = tid>>7), 8x cp16 ----
    const int lr  = tid & 127;
    const int lh  = tid >> 7;                 // 0/1: which 32B half of the 64B row
    const int swg = (lr >> 3) & 1;
    const __nv_bfloat16* gAh = Ahi + (size_t)(m0 + lr) * (size_t)K + lh * 16;
    const __nv_bfloat16* gAl = Alo + (size_t)(m0 + lr) * (size_t)K + lh * 16;
    const __nv_bfloat16* gBh = Bhi + (size_t)(n0 + lr) * (size_t)K + lh * 16;
    const __nv_bfloat16* gBl = Blo + (size_t)(n0 + lr) * (size_t)K + lh * 16;
    const uint32_t rowoff = (uint32_t)lr * ROWB;

    auto load_stage = [&](int slot, int c) {
        const uint32_t stb = sb + (uint32_t)slot * STAGE;
        const size_t koff = (size_t)c * BK;
#pragma unroll
        for (int q = 0; q < 2; ++q) {
            uint32_t sw = rowoff + (uint32_t)((lh * 2 + q) ^ swg) * 16u;
            const size_t go = koff + q * 8;
            cp16(stb + OFF_A_HI + sw, gAh + go);
            cp16(stb + OFF_A_LO + sw, gAl + go);
            cp16(stb + OFF_B_HI + sw, gBh + go);
            cp16(stb + OFF_B_LO + sw, gBl + go);
        }
    };

    float acc[4][4][4];
#pragma unroll
    for (int i = 0; i < 4; ++i)
#pragma unroll
        for (int j = 0; j < 4; ++j)
#pragma unroll
            for (int k = 0; k < 4; ++k) acc[i][j][k] = 0.0f;

    const int r15  = l & 15;
    const int half = l >> 4;

    auto compute = [&](uint32_t stageb) {
#pragma unroll
        for (int s = 0; s < 2; ++s) {
            uint32_t Ah[4][4], Al[4][4], Bh[2][4], Bl[2][4];
#pragma unroll
            for (int i = 0; i < 4; ++i) {
                int r = wm0 + i * 16 + r15;
                int chunk = (s * 2 + half) ^ ((r >> 3) & 1);
                uint32_t ad = stageb + (uint32_t)r * ROWB + (uint32_t)chunk * 16u;
                ldm4(Ah[i], ad + OFF_A_HI);
                ldm4(Al[i], ad + OFF_A_LO);
            }
#pragma unroll
            for (int p = 0; p < 2; ++p) {
                int r = wn0 + p * 16 + r15;
                int chunk = (s * 2 + half) ^ ((r >> 3) & 1);
                uint32_t bd = stageb + (uint32_t)r * ROWB + (uint32_t)chunk * 16u;
                ldm4(Bh[p], bd + OFF_B_HI);
                ldm4(Bl[p], bd + OFF_B_LO);
            }
#pragma unroll
            for (int i = 0; i < 4; ++i)
#pragma unroll
                for (int j = 0; j < 4; ++j) {
                    int p = j >> 1, t = j & 1;
                    mma16816(acc[i][j], Ah[i], Bh[p][t], Bh[p][t + 2]);
                    mma16816(acc[i][j], Ah[i], Bl[p][t], Bl[p][t + 2]);
                    mma16816(acc[i][j], Al[i], Bh[p][t], Bh[p][t + 2]);
                }
        }
    };

    const int nch = K / BK;

    // ---- prologue: fill STAGES-1 stages ----
#pragma unroll
    for (int s = 0; s < STAGES - 1; ++s) {
        load_stage(s, s);
        cp_commit();
    }

    // ---- mainloop ----
    int cur = 0;
#pragma unroll 1
    for (int c = 0; c < nch; ++c) {
        asm volatile("cp.async.wait_group %0;" :: "n"(STAGES - 2));
        __syncthreads();

        const int nx = c + STAGES - 1;
        if (nx < nch) load_stage((cur + STAGES - 1) & (STAGES - 1), nx);
        cp_commit();

        compute(sb + (uint32_t)cur * STAGE);
        cur = (cur + 1) & (STAGES - 1);
    }

    // ---- epilogue ----
    const int er = l >> 2;
    const int ec = (l & 3) * 2;
#pragma unroll
    for (int i = 0; i < 4; ++i)
#pragma unroll
        for (int j = 0; j < 4; ++j) {
            int n = n0 + wn0 + j * 8 + ec;
            float bb0 = bias[n], bb1 = bias[n + 1];
#pragma unroll
            for (int h = 0; h < 2; ++h) {
                int m = m0 + wm0 + i * 16 + er + h * 8;
                float v0 = acc[i][j][2 * h]     + bb0;
                float v1 = acc[i][j][2 * h + 1] + bb1;
                if (MODE == 1) {
                    v0 = 0.5f * v0 * (1.0f + erff(v0 * 0.70710678118654752f));
                    v1 = 0.5f * v1 * (1.0f + erff(v1 * 0.70710678118654752f));
                    uint32_t hv, lv;
                    split2(v0, v1, hv, lv);
                    *(uint32_t*)(outHi + (size_t)m * EMBED + n) = hv;
                    *(uint32_t*)(outLo + (size_t)m * EMBED + n) = lv;
                } else {
                    float2 o; o.x = v0; o.y = v1;
                    *(float2*)(out + (size_t)m * EMBED + n) = o;
                }
            }
        }
}

// ---------------- harness entry ----------------
extern "C" void kernel_launch(void* const* d_in, const int* in_sizes, int n_in,
                              void* d_out, int out_size) {
    const int*   idxs = (const int*)d_in[0];
    const float* tok  = (const float*)d_in[1];
    const float* W1   = (const float*)d_in[2];
    const float* b1   = (const float*)d_in[3];
    const float* W2   = (const float*)d_in[4];
    const float* b2   = (const float*)d_in[5];
    float* out = (float*)d_out;

    void *w1h, *w1l, *w2h, *w2l, *ah, *al, *yh, *yl;
    cudaGetSymbolAddress(&w1h, g_W1hi);
    cudaGetSymbolAddress(&w1l, g_W1lo);
    cudaGetSymbolAddress(&w2h, g_W2hi);
    cudaGetSymbolAddress(&w2l, g_W2lo);
    cudaGetSymbolAddress(&ah,  g_Ahi);
    cudaGetSymbolAddress(&al,  g_Alo);
    cudaGetSymbolAddress(&yh,  g_Yhi);
    cudaGetSymbolAddress(&yl,  g_Ylo);

    cudaFuncSetAttribute(gemm_mma<1>,
                         cudaFuncAttributeMaxDynamicSharedMemorySize, SMEM_TOTAL);
    cudaFuncSetAttribute(gemm_mma<0>,
                         cudaFuncAttributeMaxDynamicSharedMemorySize, SMEM_TOTAL);

    const int nW = EMBED * FRONT;
    convert_weights<<<(nW + 255) / 256, 256>>>(W1, W2);
    gather_split<<<TOKENS, 256>>>(tok, idxs);

    // GEMM1: A(split embed) @ W1^T + b1, GELU -> Y split bf16
    gemm_mma<1><<<dim3(EMBED / BN, TOKENS / BM), THREADS, SMEM_TOTAL>>>(
        (const __nv_bfloat16*)ah, (const __nv_bfloat16*)al,
        (const __nv_bfloat16*)w1h, (const __nv_bfloat16*)w1l, b1,
        nullptr, (__nv_bfloat16*)yh, (__nv_bfloat16*)yl, FRONT);

    // GEMM2: Y @ W2^T + b2 -> out fp32
    gemm_mma<0><<<dim3(EMBED / BN, TOKENS / BM), THREADS, SMEM_TOTAL>>>(
        (const __nv_bfloat16*)yh, (const __nv_bfloat16*)yl,
        (const __nv_bfloat16*)w2h, (const __nv_bfloat16*)w2l, b2,
        out, nullptr, nullptr, EMBED);
}

// round 7
// speedup vs baseline: 1.1121x; 1.1121x over previous
#include <cuda_runtime.h>
#include <cuda_bf16.h>
#include <cstdint>

#define FRONT 3072
#define EMBED 768
#define TOKENS 16384

// ---------------- device scratch (no dynamic alloc allowed) ----------------
__device__ __nv_bfloat16 g_W1hi[EMBED * FRONT];
__device__ __nv_bfloat16 g_W1lo[EMBED * FRONT];
__device__ __nv_bfloat16 g_W2hi[EMBED * EMBED];
__device__ __nv_bfloat16 g_W2lo[EMBED * EMBED];
__device__ __nv_bfloat16 g_Ahi[(size_t)TOKENS * FRONT];   // gathered, split embed
__device__ __nv_bfloat16 g_Alo[(size_t)TOKENS * FRONT];
__device__ __nv_bfloat16 g_Yhi[(size_t)TOKENS * EMBED];   // GELU(h1), split
__device__ __nv_bfloat16 g_Ylo[(size_t)TOKENS * EMBED];

// ---------------- tiling ----------------
constexpr int BM = 128;
constexpr int BN = 128;
constexpr int BK = 16;              // bf16 K columns per stage
constexpr int THREADS = 256;
constexpr int STAGES = 4;

// 48-byte pitch: 32B data + 16B pad. Pitch in 16B units = 3 (odd) -> the 8 rows
// of every ldmatrix 8x8 tile land on 8 distinct 16B bank groups: conflict-free,
// no XOR swizzle needed.
constexpr int ROWB  = 48;
constexpr int MAT   = 128 * ROWB;          // 6144 B
constexpr int STAGE = 4 * MAT;             // Ahi, Alo, Bhi, Blo = 24576 B
constexpr int SMEM_TOTAL = STAGES * STAGE; // 98304 B -> 2 CTAs/SM
constexpr int OFF_A_HI = 0;
constexpr int OFF_A_LO = MAT;
constexpr int OFF_B_HI = 2 * MAT;
constexpr int OFF_B_LO = 3 * MAT;

// ---------------- PTX helpers (plain compute_103-legal) ----------------
__device__ __forceinline__ uint32_t smem_u32(const void* p) {
    uint32_t a;
    asm("{ .reg .u64 t; cvta.to.shared.u64 t, %1; cvt.u32.u64 %0, t; }" : "=r"(a) : "l"(p));
    return a;
}
__device__ __forceinline__ void cp16(uint32_t s, const void* g) {
    asm volatile("cp.async.cg.shared.global [%0], [%1], 16;" :: "r"(s), "l"(g));
}
__device__ __forceinline__ void cp_commit() {
    asm volatile("cp.async.commit_group;");
}
__device__ __forceinline__ void ldm4(uint32_t r[4], uint32_t a) {
    asm volatile("ldmatrix.sync.aligned.m8n8.x4.shared.b16 {%0,%1,%2,%3}, [%4];"
                 : "=r"(r[0]), "=r"(r[1]), "=r"(r[2]), "=r"(r[3]) : "r"(a));
}
__device__ __forceinline__ void mma16816(float c[4], const uint32_t a[4],
                                         uint32_t b0, uint32_t b1) {
    asm volatile(
        "mma.sync.aligned.m16n8k16.row.col.f32.bf16.bf16.f32 "
        "{%0,%1,%2,%3}, {%4,%5,%6,%7}, {%8,%9}, {%0,%1,%2,%3};"
        : "+f"(c[0]), "+f"(c[1]), "+f"(c[2]), "+f"(c[3])
        : "r"(a[0]), "r"(a[1]), "r"(a[2]), "r"(a[3]), "r"(b0), "r"(b1));
}

__device__ __forceinline__ void split2(float x, float y, uint32_t& hi, uint32_t& lo) {
    __nv_bfloat162 h = __floats2bfloat162_rn(x, y);
    __nv_bfloat162 l = __floats2bfloat162_rn(x - __low2float(h), y - __high2float(h));
    hi = *(uint32_t*)&h;
    lo = *(uint32_t*)&l;
}

// ---------------- prep: weight split fp32 -> bf16 hi/lo ----------------
__global__ void convert_weights(const float* __restrict__ W1, const float* __restrict__ W2) {
    int i = blockIdx.x * blockDim.x + threadIdx.x;
    if (i < EMBED * FRONT) {
        float x = W1[i];
        __nv_bfloat16 h = __float2bfloat16(x);
        g_W1hi[i] = h;
        g_W1lo[i] = __float2bfloat16(x - __bfloat162float(h));
    }
    if (i < EMBED * EMBED) {
        float x = W2[i];
        __nv_bfloat16 h = __float2bfloat16(x);
        g_W2hi[i] = h;
        g_W2lo[i] = __float2bfloat16(x - __bfloat162float(h));
    }
}

// ---------------- prep: gather + split embedding rows ----------------
__global__ void __launch_bounds__(256, 4)
gather_split(const float* __restrict__ tok, const int* __restrict__ idxs) {
    const int row = blockIdx.x;
    const float4* src = (const float4*)(tok + (size_t)idxs[row] * FRONT);
    uint2* hi = (uint2*)(g_Ahi + (size_t)row * FRONT);
    uint2* lo = (uint2*)(g_Alo + (size_t)row * FRONT);
#pragma unroll
    for (int t = 0; t < FRONT / 4 / 256; ++t) {
        int i = t * 256 + threadIdx.x;
        float4 v = src[i];
        uint2 hv, lv;
        split2(v.x, v.y, hv.x, lv.x);
        split2(v.z, v.w, hv.y, lv.y);
        hi[i] = hv;
        lo[i] = lv;
    }
}

// ---------------- pure split-bf16 mma.sync GEMM, 4-stage cp.async ----------------
// acc = sum_k A[m,k]*B[n,k]   (AhBh + AhBl + AlBh)
// MODE 0: out fp32 = acc + bias
// MODE 1: v = gelu(acc + bias); write split bf16 to outHi/outLo
template <int MODE>
__global__ void __launch_bounds__(THREADS, 2)
gemm_mma(const __nv_bfloat16* __restrict__ Ahi,
         const __nv_bfloat16* __restrict__ Alo,
         const __nv_bfloat16* __restrict__ Bhi,
         const __nv_bfloat16* __restrict__ Blo,
         const float* __restrict__ bias,
         float* __restrict__ out,
         __nv_bfloat16* __restrict__ outHi,
         __nv_bfloat16* __restrict__ outLo,
         int K) {
    extern __shared__ char sm[];
    const uint32_t sb = smem_u32(sm);

    const int tid = threadIdx.x;
    const int wid = tid >> 5;
    const int l   = tid & 31;
    const int m0  = blockIdx.y * BM;
    const int n0  = blockIdx.x * BN;
    const int wm0 = (wid >> 2) * 64;
    const int wn0 = (wid & 3) * 32;

    // ---- stage loader: tid>>6 selects matrix; (tid&63) covers 2 rows x 2 chunks ----
    const int lmat = tid >> 6;            // 0=Ahi 1=Alo 2=Bhi 3=Blo
    const int lrow = (tid & 63) * 2;      // rows lrow, lrow+1
    const __nv_bfloat16* gsel =
        (lmat == 0) ? Ahi + (size_t)(m0 + lrow) * (size_t)K :
        (lmat == 1) ? Alo + (size_t)(m0 + lrow) * (size_t)K :
        (lmat == 2) ? Bhi + (size_t)(n0 + lrow) * (size_t)K :
                      Blo + (size_t)(n0 + lrow) * (size_t)K;
    const uint32_t sm_mat = (uint32_t)lmat * MAT + (uint32_t)lrow * ROWB;

    auto load_stage = [&](int slot, int c) {
        const uint32_t d = sb + (uint32_t)slot * STAGE + sm_mat;
        const __nv_bfloat16* g = gsel + (size_t)c * BK;
        cp16(d,               g);
        cp16(d + 16,          g + 8);
        cp16(d + ROWB,        g + K);
        cp16(d + ROWB + 16,   g + K + 8);
    };

    float acc[4][4][4];
#pragma unroll
    for (int i = 0; i < 4; ++i)
#pragma unroll
        for (int j = 0; j < 4; ++j)
#pragma unroll
            for (int k = 0; k < 4; ++k) acc[i][j][k] = 0.0f;

    const int r15  = l & 15;
    const int half = l >> 4;

    auto compute = [&](uint32_t stageb) {
        uint32_t Ah[4][4], Al[4][4], Bh[2][4], Bl[2][4];
#pragma unroll
        for (int i = 0; i < 4; ++i) {
            uint32_t ad = stageb + (uint32_t)(wm0 + i * 16 + r15) * ROWB
                                 + (uint32_t)half * 16u;
            ldm4(Ah[i], ad + OFF_A_HI);
            ldm4(Al[i], ad + OFF_A_LO);
        }
#pragma unroll
        for (int p = 0; p < 2; ++p) {
            uint32_t bd = stageb + (uint32_t)(wn0 + p * 16 + r15) * ROWB
                                 + (uint32_t)half * 16u;
            ldm4(Bh[p], bd + OFF_B_HI);
            ldm4(Bl[p], bd + OFF_B_LO);
        }
        // term-major: 16 independent MMAs per term -> accumulator reuse distance 16
#pragma unroll
        for (int i = 0; i < 4; ++i)
#pragma unroll
            for (int j = 0; j < 4; ++j) {
                int p = j >> 1, t = j & 1;
                mma16816(acc[i][j], Ah[i], Bh[p][t], Bh[p][t + 2]);
            }
#pragma unroll
        for (int i = 0; i < 4; ++i)
#pragma unroll
            for (int j = 0; j < 4; ++j) {
                int p = j >> 1, t = j & 1;
                mma16816(acc[i][j], Ah[i], Bl[p][t], Bl[p][t + 2]);
            }
#pragma unroll
        for (int i = 0; i < 4; ++i)
#pragma unroll
            for (int j = 0; j < 4; ++j) {
                int p = j >> 1, t = j & 1;
                mma16816(acc[i][j], Al[i], Bh[p][t], Bh[p][t + 2]);
            }
    };

    const int nch = K / BK;

    // ---- prologue: fill STAGES-1 stages ----
#pragma unroll
    for (int s = 0; s < STAGES - 1; ++s) {
        load_stage(s, s);
        cp_commit();
    }

    // ---- mainloop ----
#pragma unroll 1
    for (int c = 0; c < nch; ++c) {
        asm volatile("cp.async.wait_group %0;" :: "n"(STAGES - 2));
        __syncthreads();

        const int nx = c + STAGES - 1;
        if (nx < nch) load_stage(nx & (STAGES - 1), nx);
        cp_commit();

        compute(sb + (uint32_t)(c & (STAGES - 1)) * STAGE);
    }

    // ---- epilogue ----
    const int er = l >> 2;
    const int ec = (l & 3) * 2;
#pragma unroll
    for (int i = 0; i < 4; ++i)
#pragma unroll
        for (int j = 0; j < 4; ++j) {
            int n = n0 + wn0 + j * 8 + ec;
            float bb0 = bias[n], bb1 = bias[n + 1];
#pragma unroll
            for (int h = 0; h < 2; ++h) {
                int m = m0 + wm0 + i * 16 + er + h * 8;
                float v0 = acc[i][j][2 * h]     + bb0;
                float v1 = acc[i][j][2 * h + 1] + bb1;
                if (MODE == 1) {
                    v0 = 0.5f * v0 * (1.0f + erff(v0 * 0.70710678118654752f));
                    v1 = 0.5f * v1 * (1.0f + erff(v1 * 0.70710678118654752f));
                    uint32_t hv, lv;
                    split2(v0, v1, hv, lv);
                    *(uint32_t*)(outHi + (size_t)m * EMBED + n) = hv;
                    *(uint32_t*)(outLo + (size_t)m * EMBED + n) = lv;
                } else {
                    float2 o; o.x = v0; o.y = v1;
                    *(float2*)(out + (size_t)m * EMBED + n) = o;
                }
            }
        }
}

// ---------------- harness entry ----------------
extern "C" void kernel_launch(void* const* d_in, const int* in_sizes, int n_in,
                              void* d_out, int out_size) {
    const int*   idxs = (const int*)d_in[0];
    const float* tok  = (const float*)d_in[1];
    const float* W1   = (const float*)d_in[2];
    const float* b1   = (const float*)d_in[3];
    const float* W2   = (const float*)d_in[4];
    const float* b2   = (const float*)d_in[5];
    float* out = (float*)d_out;

    void *w1h, *w1l, *w2h, *w2l, *ah, *al, *yh, *yl;
    cudaGetSymbolAddress(&w1h, g_W1hi);
    cudaGetSymbolAddress(&w1l, g_W1lo);
    cudaGetSymbolAddress(&w2h, g_W2hi);
    cudaGetSymbolAddress(&w2l, g_W2lo);
    cudaGetSymbolAddress(&ah,  g_Ahi);
    cudaGetSymbolAddress(&al,  g_Alo);
    cudaGetSymbolAddress(&yh,  g_Yhi);
    cudaGetSymbolAddress(&yl,  g_Ylo);

    cudaFuncSetAttribute(gemm_mma<1>,
                         cudaFuncAttributeMaxDynamicSharedMemorySize, SMEM_TOTAL);
    cudaFuncSetAttribute(gemm_mma<0>,
                         cudaFuncAttributeMaxDynamicSharedMemorySize, SMEM_TOTAL);

    const int nW = EMBED * FRONT;
    convert_weights<<<(nW + 255) / 256, 256>>>(W1, W2);
    gather_split<<<TOKENS, 256>>>(tok, idxs);

    // GEMM1: A(split embed) @ W1^T + b1, GELU -> Y split bf16
    gemm_mma<1><<<dim3(EMBED / BN, TOKENS / BM), THREADS, SMEM_TOTAL>>>(
        (const __nv_bfloat16*)ah, (const __nv_bfloat16*)al,
        (const __nv_bfloat16*)w1h, (const __nv_bfloat16*)w1l, b1,
        nullptr, (__nv_bfloat16*)yh, (__nv_bfloat16*)yl, FRONT);

    // GEMM2: Y @ W2^T + b2 -> out fp32
    gemm_mma<0><<<dim3(EMBED / BN, TOKENS / BM), THREADS, SMEM_TOTAL>>>(
        (const __nv_bfloat16*)yh, (const __nv_bfloat16*)yl,
        (const __nv_bfloat16*)w2h, (const __nv_bfloat16*)w2l, b2,
        out, nullptr, nullptr, EMBED);
}